// round 3
// baseline (speedup 1.0000x reference)
#include <cuda_runtime.h>
#include <cuda_bf16.h>
#include <cstdint>

// ---------------------------------------------------------------------------
// ResidualGatedGCN — mma.sync bf16 3-term GEMMs + gated scatter
//   proj  = nf @ W + b    -> g_proj [50000,512] (h|Q|K|V)
//   ep    = ef @ We + be  -> g_ep   [600000,128]
//   out   = h ; out[r] += sigmoid(Q[r]+K[s]+ep[e]) * V[s]
// ---------------------------------------------------------------------------

#define N_NODES 50000
#define N_EDGES 600000
#define EMBED   128

__device__ float g_proj[(size_t)N_NODES * 512];     // 102.4 MB
__device__ float g_ep  [(size_t)N_EDGES * EMBED];   // 307.2 MB

// Padded SMEM tile: 128 rows x 136 bf16 (272B row stride -> conflict-free frags)
#define TPAD 136
#define TILE_BYTES (128 * TPAD * 2)        // 34816
#define GEMM_SMEM  (4 * TILE_BYTES)        // Ahi, Alo, Bhi, Blo = 139264

__device__ __forceinline__ void mma_bf16(float& d0, float& d1, float& d2, float& d3,
                                         uint32_t a0, uint32_t a1, uint32_t a2, uint32_t a3,
                                         uint32_t b0, uint32_t b1)
{
    asm volatile(
        "mma.sync.aligned.m16n8k16.row.col.f32.bf16.bf16.f32 "
        "{%0,%1,%2,%3}, {%4,%5,%6,%7}, {%8,%9}, {%0,%1,%2,%3};"
        : "+f"(d0), "+f"(d1), "+f"(d2), "+f"(d3)
        : "r"(a0), "r"(a1), "r"(a2), "r"(a3), "r"(b0), "r"(b1));
}

// ---------------------------------------------------------------------------
// C[row0:+128, col0:+128] = A[M,128] @ W[128,Nw] (+bias), fp32 via 3-term bf16.
// 256 threads = 8 warps (4M x 2N), warp tile 32x64. Single K=128 shot.
// ---------------------------------------------------------------------------
__global__ __launch_bounds__(256, 1)
void gemm128_mma(const float* __restrict__ A,
                 const float* __restrict__ W,
                 const float* __restrict__ bias,
                 float* __restrict__ C,
                 int M, int Nw)
{
    extern __shared__ char smem[];
    __nv_bfloat16* Ahi = (__nv_bfloat16*)(smem);
    __nv_bfloat16* Alo = (__nv_bfloat16*)(smem + TILE_BYTES);
    __nv_bfloat16* Bhi = (__nv_bfloat16*)(smem + 2 * TILE_BYTES);   // [n][k]
    __nv_bfloat16* Blo = (__nv_bfloat16*)(smem + 3 * TILE_BYTES);

    const int tid  = threadIdx.x;
    const int row0 = blockIdx.y * 128;
    const int col0 = blockIdx.x * 128;

    // ---- A tile: fp32 -> hi/lo bf16 (row-major, padded) ----
    for (int i = tid; i < 4096; i += 256) {
        const int r = i >> 5;
        const int c = (i & 31) * 4;
        float4 v = make_float4(0.f, 0.f, 0.f, 0.f);
        if (row0 + r < M)
            v = *(const float4*)&A[(size_t)(row0 + r) * 128 + c];
        const float vv[4] = {v.x, v.y, v.z, v.w};
        __nv_bfloat16 h[4], l[4];
        #pragma unroll
        for (int j = 0; j < 4; j++) {
            h[j] = __float2bfloat16_rn(vv[j]);
            l[j] = __float2bfloat16_rn(vv[j] - __bfloat162float(h[j]));
        }
        const int o = r * TPAD + c;
        *(__nv_bfloat162*)&Ahi[o]     = __nv_bfloat162(h[0], h[1]);
        *(__nv_bfloat162*)&Ahi[o + 2] = __nv_bfloat162(h[2], h[3]);
        *(__nv_bfloat162*)&Alo[o]     = __nv_bfloat162(l[0], l[1]);
        *(__nv_bfloat162*)&Alo[o + 2] = __nv_bfloat162(l[2], l[3]);
    }

    // ---- B tile: W[k, col0+n] -> Bs[n][k] transposed hi/lo ----
    for (int i = tid; i < 4096; i += 256) {
        const int k  = i >> 5;
        const int n4 = (i & 31) * 4;
        const float4 v = *(const float4*)&W[(size_t)k * Nw + col0 + n4];
        const float vv[4] = {v.x, v.y, v.z, v.w};
        #pragma unroll
        for (int j = 0; j < 4; j++) {
            __nv_bfloat16 h = __float2bfloat16_rn(vv[j]);
            __nv_bfloat16 l = __float2bfloat16_rn(vv[j] - __bfloat162float(h));
            Bhi[(n4 + j) * TPAD + k] = h;
            Blo[(n4 + j) * TPAD + k] = l;
        }
    }
    __syncthreads();

    const int wid  = tid >> 5;
    const int lane = tid & 31;
    const int g    = lane >> 2;          // 0..7
    const int t    = lane & 3;           // 0..3
    const int wm   = wid >> 1;           // 0..3
    const int wn   = wid & 1;            // 0..1

    float acc[2][8][4];
    #pragma unroll
    for (int m = 0; m < 2; m++)
        #pragma unroll
        for (int n = 0; n < 8; n++)
            #pragma unroll
            for (int j = 0; j < 4; j++) acc[m][n][j] = 0.f;

    #pragma unroll
    for (int ks = 0; ks < 8; ks++) {
        const int k0 = ks * 16;
        uint32_t ah[2][4], al[2][4];
        #pragma unroll
        for (int m = 0; m < 2; m++) {
            const int rb = wm * 32 + m * 16;
            const int o00 = (rb + g)     * TPAD + k0 + 2 * t;
            const int o10 = (rb + g + 8) * TPAD + k0 + 2 * t;
            ah[m][0] = *(const uint32_t*)&Ahi[o00];
            ah[m][1] = *(const uint32_t*)&Ahi[o10];
            ah[m][2] = *(const uint32_t*)&Ahi[o00 + 8];
            ah[m][3] = *(const uint32_t*)&Ahi[o10 + 8];
            al[m][0] = *(const uint32_t*)&Alo[o00];
            al[m][1] = *(const uint32_t*)&Alo[o10];
            al[m][2] = *(const uint32_t*)&Alo[o00 + 8];
            al[m][3] = *(const uint32_t*)&Alo[o10 + 8];
        }
        #pragma unroll
        for (int n = 0; n < 8; n++) {
            const int nb = wn * 64 + n * 8 + g;
            const int ob = nb * TPAD + k0 + 2 * t;
            const uint32_t bh0 = *(const uint32_t*)&Bhi[ob];
            const uint32_t bh1 = *(const uint32_t*)&Bhi[ob + 8];
            const uint32_t bl0 = *(const uint32_t*)&Blo[ob];
            const uint32_t bl1 = *(const uint32_t*)&Blo[ob + 8];
            #pragma unroll
            for (int m = 0; m < 2; m++) {
                float* d = acc[m][n];
                mma_bf16(d[0], d[1], d[2], d[3],
                         ah[m][0], ah[m][1], ah[m][2], ah[m][3], bh0, bh1);
                mma_bf16(d[0], d[1], d[2], d[3],
                         ah[m][0], ah[m][1], ah[m][2], ah[m][3], bl0, bl1);
                mma_bf16(d[0], d[1], d[2], d[3],
                         al[m][0], al[m][1], al[m][2], al[m][3], bh0, bh1);
            }
        }
    }

    // ---- epilogue: bias + store ----
    float2 bvs[8];
    #pragma unroll
    for (int n = 0; n < 8; n++) {
        const int bc = col0 + wn * 64 + n * 8 + 2 * t;
        bvs[n] = *(const float2*)&bias[bc];
    }
    #pragma unroll
    for (int m = 0; m < 2; m++) {
        const int r0 = row0 + wm * 32 + m * 16 + g;
        const int r1 = r0 + 8;
        #pragma unroll
        for (int n = 0; n < 8; n++) {
            const int cc = col0 + wn * 64 + n * 8 + 2 * t;
            if (r0 < M) {
                float2 o0 = make_float2(acc[m][n][0] + bvs[n].x,
                                        acc[m][n][1] + bvs[n].y);
                *(float2*)&C[(size_t)r0 * Nw + cc] = o0;
            }
            if (r1 < M) {
                float2 o1 = make_float2(acc[m][n][2] + bvs[n].x,
                                        acc[m][n][3] + bvs[n].y);
                *(float2*)&C[(size_t)r1 * Nw + cc] = o1;
            }
        }
    }
}

// ---------------------------------------------------------------------------
// out[n,:] = h[n,:] = g_proj[n, 0:128]
// ---------------------------------------------------------------------------
__global__ void init_out_kernel(float* __restrict__ out)
{
    int i = blockIdx.x * blockDim.x + threadIdx.x;
    if (i < N_NODES * 32) {
        int row = i >> 5;
        int c4  = i & 31;
        float4 v = *(const float4*)&g_proj[(size_t)row * 512 + c4 * 4];
        ((float4*)out)[i] = v;
    }
}

// ---------------------------------------------------------------------------
// Per-edge gated scatter: one warp per edge, float4 per lane.
// ---------------------------------------------------------------------------
__device__ __forceinline__ float sigmoidf_(float x) {
    return 1.0f / (1.0f + expf(-x));
}

__global__ __launch_bounds__(256)
void edge_scatter_kernel(const int* __restrict__ senders,
                         const int* __restrict__ receivers,
                         float* __restrict__ out)
{
    const int warp = (blockIdx.x * blockDim.x + threadIdx.x) >> 5;
    const int lane = threadIdx.x & 31;
    if (warp >= N_EDGES) return;
    const int e = warp;

    const int s = __ldg(&senders[e]);
    const int r = __ldg(&receivers[e]);
    const int d = lane * 4;

    const float4 ep = *(const float4*)&g_ep  [(size_t)e * 128 + d];
    const float4 q  = *(const float4*)&g_proj[(size_t)r * 512 + 128 + d];
    const float4 kk = *(const float4*)&g_proj[(size_t)s * 512 + 256 + d];
    const float4 v  = *(const float4*)&g_proj[(size_t)s * 512 + 384 + d];

    float4 m;
    m.x = sigmoidf_(q.x + kk.x + ep.x) * v.x;
    m.y = sigmoidf_(q.y + kk.y + ep.y) * v.y;
    m.z = sigmoidf_(q.z + kk.z + ep.z) * v.z;
    m.w = sigmoidf_(q.w + kk.w + ep.w) * v.w;

    float* o = &out[(size_t)r * 128 + d];
    atomicAdd(o + 0, m.x);
    atomicAdd(o + 1, m.y);
    atomicAdd(o + 2, m.z);
    atomicAdd(o + 3, m.w);
}

// ---------------------------------------------------------------------------
// Launch
// Inputs: 0 nf[50000,128] 1 snd[600000] 2 rcv[600000] 3 ef[600000,128]
//         4 Wk[128,512] 5 Wb[512] 6 Wek[128,128] 7 Web[128]
// ---------------------------------------------------------------------------
extern "C" void kernel_launch(void* const* d_in, const int* in_sizes, int n_in,
                              void* d_out, int out_size)
{
    const float* nf   = (const float*)d_in[0];
    const int*   snd  = (const int*)  d_in[1];
    const int*   rcv  = (const int*)  d_in[2];
    const float* ef   = (const float*)d_in[3];
    const float* Wk   = (const float*)d_in[4];
    const float* Wb   = (const float*)d_in[5];
    const float* Wek  = (const float*)d_in[6];
    const float* Web  = (const float*)d_in[7];
    float* out = (float*)d_out;

    float* proj_ptr;
    float* ep_ptr;
    cudaGetSymbolAddress((void**)&proj_ptr, g_proj);
    cudaGetSymbolAddress((void**)&ep_ptr,   g_ep);

    static bool attr_set = false;
    if (!attr_set) {
        cudaFuncSetAttribute(gemm128_mma,
                             cudaFuncAttributeMaxDynamicSharedMemorySize,
                             GEMM_SMEM);
        attr_set = true;
    }

    // 1) node projection [50000,512]
    {
        dim3 grid(4, (N_NODES + 127) / 128);
        gemm128_mma<<<grid, 256, GEMM_SMEM>>>(nf, Wk, Wb, proj_ptr, N_NODES, 512);
    }
    // 2) edge projection [600000,128]
    {
        dim3 grid(1, (N_EDGES + 127) / 128);
        gemm128_mma<<<grid, 256, GEMM_SMEM>>>(ef, Wek, Web, ep_ptr, N_EDGES, 128);
    }
    // 3) out = h
    {
        int total = N_NODES * 32;
        init_out_kernel<<<(total + 255) / 256, 256>>>(out);
    }
    // 4) gated scatter
    {
        int blocks = (N_EDGES * 32 + 255) / 256;
        edge_scatter_kernel<<<blocks, 256>>>(snd, rcv, out);
    }
}

// round 5
// speedup vs baseline: 2.8912x; 2.8912x over previous
#include <cuda_runtime.h>
#include <cuda_bf16.h>
#include <cstdint>

// ---------------------------------------------------------------------------
// ResidualGatedGCN — tf32 mma.sync pipelined GEMMs + v4-red gated scatter
// ---------------------------------------------------------------------------

#define N_NODES 50000
#define N_EDGES 600000
#define EMBED   128

__device__ float g_proj[(size_t)N_NODES * 512];     // 102.4 MB
__device__ float g_ep  [(size_t)N_EDGES * EMBED];   // 307.2 MB

// GEMM tiling: CTA computes 128x128, K=128 in 4 chunks of 32.
#define KC      32
#define APAD    36                       // fp32 per A-chunk row
#define BPAD    132                      // fp32 per B row (k-major)
#define A_CHUNK_BYTES (128 * APAD * 4)   // 18432
#define B_BYTES       (128 * BPAD * 4)   // 67584
#define GEMM_SMEM     (B_BYTES + 2 * A_CHUNK_BYTES)   // 104448 -> 2 CTAs/SM

__device__ __forceinline__ uint32_t smem_u32(const void* p) {
    uint32_t a;
    asm("{ .reg .u64 t; cvta.to.shared.u64 t, %1; cvt.u32.u64 %0, t; }"
        : "=r"(a) : "l"(p));
    return a;
}
__device__ __forceinline__ uint32_t f2tf32(float f) {
    uint32_t u;
    asm("cvt.rna.tf32.f32 %0, %1;" : "=r"(u) : "f"(f));
    return u;
}
__device__ __forceinline__ void mma_tf32(float& d0, float& d1, float& d2, float& d3,
                                         uint32_t a0, uint32_t a1, uint32_t a2, uint32_t a3,
                                         uint32_t b0, uint32_t b1)
{
    asm volatile(
        "mma.sync.aligned.m16n8k8.row.col.f32.tf32.tf32.f32 "
        "{%0,%1,%2,%3}, {%4,%5,%6,%7}, {%8,%9}, {%0,%1,%2,%3};"
        : "+f"(d0), "+f"(d1), "+f"(d2), "+f"(d3)
        : "r"(a0), "r"(a1), "r"(a2), "r"(a3), "r"(b0), "r"(b1));
}
__device__ __forceinline__ void cp_async16(uint32_t sdst, const void* gsrc, int bytes) {
    asm volatile("cp.async.cg.shared.global [%0], [%1], 16, %2;"
                 :: "r"(sdst), "l"(gsrc), "r"(bytes));
}
__device__ __forceinline__ void cp_commit() {
    asm volatile("cp.async.commit_group;" ::: "memory");
}

// ---------------------------------------------------------------------------
// C[row0:+128, col0:+128] = A[M,128] @ W[128,Nw] + bias (fp32 via tf32 MMA)
// 256 threads, 8 warps (4M x 2N), warp tile 32x64.
// ---------------------------------------------------------------------------
__global__ __launch_bounds__(256, 2)
void gemm_tf32(const float* __restrict__ A,
               const float* __restrict__ W,
               const float* __restrict__ bias,
               float* __restrict__ C,
               int M, int Nw)
{
    extern __shared__ char smem[];
    uint32_t* Bs = (uint32_t*)smem;                       // [k][n] tf32, BPAD stride
    float* Abuf[2] = { (float*)(smem + B_BYTES),
                       (float*)(smem + B_BYTES + A_CHUNK_BYTES) };
    const uint32_t sbase = smem_u32(smem);
    const uint32_t a_s[2] = { sbase + B_BYTES, sbase + B_BYTES + A_CHUNK_BYTES };

    const int tid  = threadIdx.x;
    const int row0 = blockIdx.y * 128;
    const int col0 = blockIdx.x * 128;

    // ---- async copy of one A chunk (128 x 32 fp32), zero-fill OOB rows ----
    auto copyA = [&](int chunk, uint32_t sdst) {
        #pragma unroll
        for (int j = 0; j < 4; j++) {
            const int idx = tid + j * 256;     // 1024 16B segments
            const int r   = idx >> 3;
            const int seg = idx & 7;
            const int gr  = row0 + r;
            const int bytes = (gr < M) ? 16 : 0;
            const int grc = (gr < M) ? gr : (M - 1);
            const float* src = A + (size_t)grc * 128 + chunk * KC + seg * 4;
            cp_async16(sdst + (r * APAD + seg * 4) * 4, src, bytes);
        }
    };

    copyA(0, a_s[0]); cp_commit();

    // ---- stage B: W[k][col0+n] -> Bs[k][n] tf32 ----
    #pragma unroll
    for (int it = 0; it < 16; it++) {
        const int idx = tid + it * 256;       // 4096 float4 quads
        const int k   = idx >> 5;
        const int n4  = (idx & 31) * 4;
        const float4 v = *(const float4*)&W[(size_t)k * Nw + col0 + n4];
        uint4 o;
        o.x = f2tf32(v.x); o.y = f2tf32(v.y); o.z = f2tf32(v.z); o.w = f2tf32(v.w);
        *(uint4*)&Bs[k * BPAD + n4] = o;
    }

    copyA(1, a_s[1]); cp_commit();

    const int wid  = tid >> 5;
    const int lane = tid & 31;
    const int g    = lane >> 2;          // 0..7
    const int t    = lane & 3;           // 0..3
    const int wm   = wid >> 1;           // 0..3
    const int wn   = wid & 1;            // 0..1

    float acc[2][8][4];
    #pragma unroll
    for (int m = 0; m < 2; m++)
        #pragma unroll
        for (int n = 0; n < 8; n++)
            #pragma unroll
            for (int j = 0; j < 4; j++) acc[m][n][j] = 0.f;

    // compute one 32-wide K chunk from buffer `Ab`; kb = global K base of chunk
    auto compute_chunk = [&](const float* __restrict__ Ab, int kb) {
        #pragma unroll
        for (int ks = 0; ks < 4; ks++) {
            const int k0 = ks * 8;
            uint32_t af[2][4];
            #pragma unroll
            for (int m = 0; m < 2; m++) {
                const int rb = wm * 32 + m * 16 + g;
                const float* p0 = Ab + rb * APAD + k0 + t;
                const float* p1 = Ab + (rb + 8) * APAD + k0 + t;
                af[m][0] = f2tf32(p0[0]);
                af[m][1] = f2tf32(p1[0]);
                af[m][2] = f2tf32(p0[4]);
                af[m][3] = f2tf32(p1[4]);
            }
            #pragma unroll
            for (int n = 0; n < 8; n++) {
                const int nidx = wn * 64 + n * 8 + g;
                const uint32_t b0 = Bs[(kb + k0 + t) * BPAD + nidx];       // FIX: +kb
                const uint32_t b1 = Bs[(kb + k0 + t + 4) * BPAD + nidx];   // FIX: +kb
                #pragma unroll
                for (int m = 0; m < 2; m++)
                    mma_tf32(acc[m][n][0], acc[m][n][1], acc[m][n][2], acc[m][n][3],
                             af[m][0], af[m][1], af[m][2], af[m][3], b0, b1);
            }
        }
    };

    // ---- pipelined chunks ----
    asm volatile("cp.async.wait_group 1;" ::: "memory");
    __syncthreads();                        // chunk0 + B staged
    compute_chunk(Abuf[0], 0);
    __syncthreads();
    copyA(2, a_s[0]); cp_commit();

    asm volatile("cp.async.wait_group 1;" ::: "memory");
    __syncthreads();
    compute_chunk(Abuf[1], 32);
    __syncthreads();
    copyA(3, a_s[1]); cp_commit();

    asm volatile("cp.async.wait_group 1;" ::: "memory");
    __syncthreads();
    compute_chunk(Abuf[0], 64);

    asm volatile("cp.async.wait_group 0;" ::: "memory");
    __syncthreads();
    compute_chunk(Abuf[1], 96);

    // ---- epilogue: bias + store ----
    float2 bvs[8];
    #pragma unroll
    for (int n = 0; n < 8; n++)
        bvs[n] = *(const float2*)&bias[col0 + wn * 64 + n * 8 + 2 * t];

    #pragma unroll
    for (int m = 0; m < 2; m++) {
        const int r0 = row0 + wm * 32 + m * 16 + g;
        const int r1 = r0 + 8;
        #pragma unroll
        for (int n = 0; n < 8; n++) {
            const int cc = col0 + wn * 64 + n * 8 + 2 * t;
            if (r0 < M)
                *(float2*)&C[(size_t)r0 * Nw + cc] =
                    make_float2(acc[m][n][0] + bvs[n].x, acc[m][n][1] + bvs[n].y);
            if (r1 < M)
                *(float2*)&C[(size_t)r1 * Nw + cc] =
                    make_float2(acc[m][n][2] + bvs[n].x, acc[m][n][3] + bvs[n].y);
        }
    }
}

// ---------------------------------------------------------------------------
// out[n,:] = h[n,:] = g_proj[n, 0:128]
// ---------------------------------------------------------------------------
__global__ void init_out_kernel(float* __restrict__ out)
{
    int i = blockIdx.x * blockDim.x + threadIdx.x;
    if (i < N_NODES * 32) {
        int row = i >> 5;
        int c4  = i & 31;
        float4 v = *(const float4*)&g_proj[(size_t)row * 512 + c4 * 4];
        ((float4*)out)[i] = v;
    }
}

// ---------------------------------------------------------------------------
// Per-edge gated scatter: one warp per edge, float4 per lane, v4 red.
// ---------------------------------------------------------------------------
__device__ __forceinline__ float sigmoidf_(float x) {
    return 1.0f / (1.0f + __expf(-x));
}

__global__ __launch_bounds__(256)
void edge_scatter_kernel(const int* __restrict__ senders,
                         const int* __restrict__ receivers,
                         float* __restrict__ out)
{
    const int warp = (blockIdx.x * blockDim.x + threadIdx.x) >> 5;
    const int lane = threadIdx.x & 31;
    if (warp >= N_EDGES) return;
    const int e = warp;

    const int s = __ldg(&senders[e]);
    const int r = __ldg(&receivers[e]);
    const int d = lane * 4;

    const float4 ep = *(const float4*)&g_ep  [(size_t)e * 128 + d];
    const float4 q  = *(const float4*)&g_proj[(size_t)r * 512 + 128 + d];
    const float4 kk = *(const float4*)&g_proj[(size_t)s * 512 + 256 + d];
    const float4 v  = *(const float4*)&g_proj[(size_t)s * 512 + 384 + d];

    float4 m;
    m.x = sigmoidf_(q.x + kk.x + ep.x) * v.x;
    m.y = sigmoidf_(q.y + kk.y + ep.y) * v.y;
    m.z = sigmoidf_(q.z + kk.z + ep.z) * v.z;
    m.w = sigmoidf_(q.w + kk.w + ep.w) * v.w;

    float* o = &out[(size_t)r * 128 + d];
    asm volatile("red.global.add.v4.f32 [%0], {%1,%2,%3,%4};"
                 :: "l"(o), "f"(m.x), "f"(m.y), "f"(m.z), "f"(m.w)
                 : "memory");
}

// ---------------------------------------------------------------------------
// Launch
// Inputs: 0 nf[50000,128] 1 snd[600000] 2 rcv[600000] 3 ef[600000,128]
//         4 Wk[128,512] 5 Wb[512] 6 Wek[128,128] 7 Web[128]
// ---------------------------------------------------------------------------
extern "C" void kernel_launch(void* const* d_in, const int* in_sizes, int n_in,
                              void* d_out, int out_size)
{
    const float* nf   = (const float*)d_in[0];
    const int*   snd  = (const int*)  d_in[1];
    const int*   rcv  = (const int*)  d_in[2];
    const float* ef   = (const float*)d_in[3];
    const float* Wk   = (const float*)d_in[4];
    const float* Wb   = (const float*)d_in[5];
    const float* Wek  = (const float*)d_in[6];
    const float* Web  = (const float*)d_in[7];
    float* out = (float*)d_out;

    float* proj_ptr;
    float* ep_ptr;
    cudaGetSymbolAddress((void**)&proj_ptr, g_proj);
    cudaGetSymbolAddress((void**)&ep_ptr,   g_ep);

    cudaFuncSetAttribute(gemm_tf32,
                         cudaFuncAttributeMaxDynamicSharedMemorySize,
                         GEMM_SMEM);

    // 1) node projection [50000,512]
    {
        dim3 grid(4, (N_NODES + 127) / 128);
        gemm_tf32<<<grid, 256, GEMM_SMEM>>>(nf, Wk, Wb, proj_ptr, N_NODES, 512);
    }
    // 2) edge projection [600000,128]
    {
        dim3 grid(1, (N_EDGES + 127) / 128);
        gemm_tf32<<<grid, 256, GEMM_SMEM>>>(ef, Wek, Web, ep_ptr, N_EDGES, 128);
    }
    // 3) out = h
    {
        int total = N_NODES * 32;
        init_out_kernel<<<(total + 255) / 256, 256>>>(out);
    }
    // 4) gated scatter
    {
        int blocks = (N_EDGES * 32 + 255) / 256;
        edge_scatter_kernel<<<blocks, 256>>>(snd, rcv, out);
    }
}